// round 10
// baseline (speedup 1.0000x reference)
#include <cuda_runtime.h>
#include <cstdint>

// Problem constants
#define N_NODES 2048
#define NF4     512             // N_NODES/4 float4 columns
#define K_TOTAL 3072            // B*L
#define KC      64              // k rows per block chunk
#define NKC     48              // chunks (KC*NKC == K_TOTAL)
#define NBN     4               // n blocks (128 f4-cols each)
#define SR      4               // rows per TMA stage
#define NSTG    (KC / SR)       // 16 stages
#define RING    4               // ring depth
#define STG_BYTES (SR * 128 * 16)   // 8192 bytes per stage
#define ROWS    3072

// Scratch device globals (no allocation allowed). Fully overwritten each launch.
__device__ float g_part[NKC * 8 * N_NODES];   // 3 MB partial conv sums
__device__ float g_per_node[N_NODES];         // 8 KB per-node scalars

// ---- helpers ---------------------------------------------------------------
__device__ __forceinline__ unsigned smem_u32(const void* p) {
    unsigned a;
    asm("{ .reg .u64 t; cvta.to.shared.u64 t, %1; cvt.u32.u64 %0, t; }"
        : "=r"(a) : "l"(p));
    return a;
}
__device__ __forceinline__ void mbar_init(unsigned mb, unsigned cnt) {
    asm volatile("mbarrier.init.shared.b64 [%0], %1;" :: "r"(mb), "r"(cnt) : "memory");
}
__device__ __forceinline__ void mbar_expect_tx(unsigned mb, unsigned bytes) {
    asm volatile("mbarrier.arrive.expect_tx.shared.b64 _, [%0], %1;"
                 :: "r"(mb), "r"(bytes) : "memory");
}
__device__ __forceinline__ void bulk_g2s(unsigned sdst, const void* gsrc,
                                         unsigned bytes, unsigned mb) {
    asm volatile(
        "cp.async.bulk.shared::cluster.global.mbarrier::complete_tx::bytes "
        "[%0], [%1], %2, [%3];"
        :: "r"(sdst), "l"(gsrc), "r"(bytes), "r"(mb) : "memory");
}
__device__ __forceinline__ void mbar_wait(unsigned mb, unsigned parity) {
    asm volatile(
        "{\n\t"
        ".reg .pred P;\n\t"
        "W%=:\n\t"
        "mbarrier.try_wait.parity.acquire.cta.shared::cta.b64 P, [%0], %1, 0x989680;\n\t"
        "@!P bra W%=;\n\t"
        "}"
        :: "r"(mb), "r"(parity) : "memory");
}
__device__ __forceinline__ unsigned long long pack2(float a, float b) {
    unsigned long long r;
    asm("mov.b64 %0, {%1, %2};" : "=l"(r) : "f"(a), "f"(b));
    return r;
}
__device__ __forceinline__ void fma2n(unsigned long long& d,
                                      unsigned long long a,
                                      unsigned long long b) {
    asm("fma.rn.f32x2 %0, %1, %2, %0;" : "+l"(d) : "l"(a), "l"(b));
}
__device__ __forceinline__ void unpack2(unsigned long long v, float& a, float& b) {
    asm("mov.b64 {%0, %1}, %2;" : "=f"(a), "=f"(b) : "l"(v));
}
__device__ __forceinline__ float ldg1v(const float* p) {
    float v;
    asm volatile("ld.global.nc.f32 %0, [%1];" : "=f"(v) : "l"(p));
    return v;
}

// ---------------------------------------------------------------------------
// K1: partial skinny GEMM with TMA bulk staging.
// Block = 128 f4-cols x KC=64 rows; 16 stages of 4 rows (8KB) in a 4-deep
// ring; one elected thread issues 4 x 2KB cp.async.bulk per stage.
// Thread (ln = tid&127, q = tid>>7) consumes 2 rows/stage out of SMEM.
// Cross-half reduction buffer ALIASES the ring (dead after mainloop).
// grid = (4, 48) x 256 threads.
// ---------------------------------------------------------------------------
__global__ __launch_bounds__(256) void k_gemm_partial(
    const float4* __restrict__ x4, const float* __restrict__ Wc)
{
    __shared__ alignas(128) char ring[RING * STG_BYTES];          // 32 KB
    __shared__ alignas(16) float sWd[KC * 16];                    // 4 KB
    __shared__ alignas(8) unsigned long long mbar[RING];

    const int tid  = threadIdx.x;
    const int ln   = tid & 127;                  // f4-col within block
    const int q    = tid >> 7;                   // row-half 0..1
    const int nblk = blockIdx.x;                 // 0..3
    const int kblk = blockIdx.y;                 // 0..47
    const int k0   = kblk * KC;

    // stage Wc chunk, duplicated into f32x2 pairs
    const float* wsrc = Wc + (size_t)k0 * 8;
    #pragma unroll
    for (int i = tid; i < KC * 16; i += 256) sWd[i] = wsrc[i >> 1];

    const unsigned ring0 = smem_u32(ring);
    const unsigned mb0   = smem_u32(mbar);
    const char* gbase = reinterpret_cast<const char*>(x4)
                      + ((size_t)k0 * NF4 + nblk * 128) * 16;

    if (tid == 0) {
        #pragma unroll
        for (int m = 0; m < RING; m++) mbar_init(mb0 + m * 8, 1);
    }
    __syncthreads();

    // prologue: stages 0..2 in flight
    if (tid == 0) {
        #pragma unroll
        for (int s = 0; s < 3; s++) {
            unsigned mb = mb0 + (s % RING) * 8;
            mbar_expect_tx(mb, STG_BYTES);
            #pragma unroll
            for (int r = 0; r < SR; r++)
                bulk_g2s(ring0 + (s % RING) * STG_BYTES + r * 2048,
                         gbase + ((size_t)(s * SR + r)) * (NF4 * 16),
                         2048, mb);
        }
    }

    unsigned long long accp[2][8];               // [rr][j]
    #pragma unroll
    for (int p = 0; p < 2; p++)
        #pragma unroll
        for (int j = 0; j < 8; j++) accp[p][j] = 0ull;

    const ulonglong2* wp = reinterpret_cast<const ulonglong2*>(sWd);

    #pragma unroll
    for (int s = 0; s < NSTG; s++) {
        if (tid == 0 && s + 3 < NSTG) {          // issue stage s+3
            const int t = s + 3;
            unsigned mb = mb0 + (t % RING) * 8;
            mbar_expect_tx(mb, STG_BYTES);
            #pragma unroll
            for (int r = 0; r < SR; r++)
                bulk_g2s(ring0 + (t % RING) * STG_BYTES + r * 2048,
                         gbase + ((size_t)(t * SR + r)) * (NF4 * 16),
                         2048, mb);
        }
        mbar_wait(mb0 + (s % RING) * 8, (s >> 2) & 1);

        const float4* st = reinterpret_cast<const float4*>(
            ring + (s % RING) * STG_BYTES);
        #pragma unroll
        for (int rr = 0; rr < 2; rr++) {         // consume 2 rows
            const int row = q * 2 + rr;
            float4 xv = st[row * 128 + ln];
            unsigned long long lo = pack2(xv.x, xv.y);
            unsigned long long hi = pack2(xv.z, xv.w);
            const ulonglong2* w = wp + (size_t)(s * SR + row) * 4;
            #pragma unroll
            for (int jj = 0; jj < 4; jj++) {
                ulonglong2 wv = w[jj];           // broadcast LDS.128
                fma2n(accp[rr][2 * jj],     lo, wv.x);
                fma2n(accp[rr][2 * jj + 1], lo, wv.y);
                // hi part accumulates into same acc via second f32x2 lane pair:
                // handled below (separate accumulators for hi)
            }
            // hi lanes
            const ulonglong2* w2 = wp + (size_t)(s * SR + row) * 4;
            (void)w2;
            #pragma unroll
            for (int jj = 0; jj < 4; jj++) {
                ulonglong2 wv = w[jj];
                fma2n(accp[rr][2 * jj],     hi, 0ull), (void)0; // placeholder
            }
        }
        __syncthreads();                         // ring slot reusable
    }

    // NOTE: the loop above is replaced below — see corrected consume loop.
    (void)0;
}

// The kernel above contains a placeholder error — real implementation follows.
// (kept minimal: the actual k_gemm used is k_gemm_partial2)

__global__ __launch_bounds__(256) void k_gemm_partial2(
    const float4* __restrict__ x4, const float* __restrict__ Wc)
{
    __shared__ alignas(128) char ring[RING * STG_BYTES];          // 32 KB
    __shared__ alignas(16) float sWd[KC * 16];                    // 4 KB
    __shared__ alignas(8) unsigned long long mbar[RING];

    const int tid  = threadIdx.x;
    const int ln   = tid & 127;
    const int q    = tid >> 7;
    const int nblk = blockIdx.x;
    const int kblk = blockIdx.y;
    const int k0   = kblk * KC;

    const float* wsrc = Wc + (size_t)k0 * 8;
    #pragma unroll
    for (int i = tid; i < KC * 16; i += 256) sWd[i] = wsrc[i >> 1];

    const unsigned ring0 = smem_u32(ring);
    const unsigned mb0   = smem_u32(mbar);
    const char* gbase = reinterpret_cast<const char*>(x4)
                      + ((size_t)k0 * NF4 + nblk * 128) * 16;

    if (tid == 0) {
        #pragma unroll
        for (int m = 0; m < RING; m++) mbar_init(mb0 + m * 8, 1);
    }
    __syncthreads();

    if (tid == 0) {
        #pragma unroll
        for (int s = 0; s < 3; s++) {
            unsigned mb = mb0 + (s % RING) * 8;
            mbar_expect_tx(mb, STG_BYTES);
            #pragma unroll
            for (int r = 0; r < SR; r++)
                bulk_g2s(ring0 + (s % RING) * STG_BYTES + r * 2048,
                         gbase + ((size_t)(s * SR + r)) * (NF4 * 16),
                         2048, mb);
        }
    }

    // accumulators: [pair: lo(nodes 0,1)/hi(nodes 2,3)][j], summed over BOTH
    // rows this thread consumes per stage (rows belong to same k-sum).
    unsigned long long accp[2][8];
    #pragma unroll
    for (int p = 0; p < 2; p++)
        #pragma unroll
        for (int j = 0; j < 8; j++) accp[p][j] = 0ull;

    const ulonglong2* wp = reinterpret_cast<const ulonglong2*>(sWd);

    #pragma unroll
    for (int s = 0; s < NSTG; s++) {
        if (tid == 0 && s + 3 < NSTG) {
            const int t = s + 3;
            unsigned mb = mb0 + (t % RING) * 8;
            mbar_expect_tx(mb, STG_BYTES);
            #pragma unroll
            for (int r = 0; r < SR; r++)
                bulk_g2s(ring0 + (t % RING) * STG_BYTES + r * 2048,
                         gbase + ((size_t)(t * SR + r)) * (NF4 * 16),
                         2048, mb);
        }
        mbar_wait(mb0 + (s % RING) * 8, (s >> 2) & 1);

        const float4* st = reinterpret_cast<const float4*>(
            ring + (s % RING) * STG_BYTES);
        #pragma unroll
        for (int rr = 0; rr < 2; rr++) {
            const int row = q * 2 + rr;
            float4 xv = st[row * 128 + ln];
            unsigned long long lo = pack2(xv.x, xv.y);
            unsigned long long hi = pack2(xv.z, xv.w);
            const ulonglong2* w = wp + (size_t)(s * SR + row) * 4;
            #pragma unroll
            for (int jj = 0; jj < 4; jj++) {
                ulonglong2 wv = w[jj];
                fma2n(accp[0][2 * jj],     lo, wv.x);
                fma2n(accp[1][2 * jj],     hi, wv.x);
                fma2n(accp[0][2 * jj + 1], lo, wv.y);
                fma2n(accp[1][2 * jj + 1], hi, wv.y);
            }
        }
        __syncthreads();
    }

    // Ring dead: reuse as cross-half reduction buffer (128 cols x 8 f4 = 16KB).
    float4* sred = reinterpret_cast<float4*>(ring);
    if (q == 1) {
        #pragma unroll
        for (int j = 0; j < 8; j++) {
            float4 o;
            unpack2(accp[0][j], o.x, o.y);
            unpack2(accp[1][j], o.z, o.w);
            sred[ln * 8 + j] = o;
        }
    }
    __syncthreads();
    if (q == 0) {
        float4* gp4 = reinterpret_cast<float4*>(g_part);
        #pragma unroll
        for (int j = 0; j < 8; j++) {
            float4 o;
            unpack2(accp[0][j], o.x, o.y);
            unpack2(accp[1][j], o.z, o.w);
            float4 r = sred[ln * 8 + j];
            o.x += r.x; o.y += r.y; o.z += r.z; o.w += r.w;
            gp4[(size_t)(kblk * 8 + j) * NF4 + nblk * 128 + ln] = o;
        }
    }
}

// ---------------------------------------------------------------------------
// K2: reduce 48 partials per (n,j), add bc, folded MLP, write per_node[n].
// grid = 32 x 256; block = 64 nodes x 4 k-slices (12 chunks each).
// ---------------------------------------------------------------------------
__global__ __launch_bounds__(256) void k_reduce_mlp(
    const float* __restrict__ bc, const float* __restrict__ W1,
    const float* __restrict__ b1, const float* __restrict__ W2,
    const float* __restrict__ b2)
{
    __shared__ float sWeff[256];
    __shared__ float sb1[32];
    __shared__ float sW2v[32];
    __shared__ float sred[3 * 64 * 9];

    const int tid = threadIdx.x;
    const int ln  = tid & 63;
    const int q   = tid >> 6;
    const int n   = blockIdx.x * 64 + ln;

    sWeff[tid] = W1[tid] + W1[tid + 256];
    if (tid < 32) { sb1[tid] = b1[tid]; sW2v[tid] = W2[tid]; }

    float conv[8];
    #pragma unroll
    for (int j = 0; j < 8; j++) conv[j] = 0.0f;

    const int kc0 = q * 12;
    #pragma unroll
    for (int kc = kc0; kc < kc0 + 12; kc++) {
        const float* p = g_part + (size_t)(kc * 8) * N_NODES + n;
        float v[8];
        #pragma unroll
        for (int j = 0; j < 8; j++)
            v[j] = ldg1v(p + (size_t)j * N_NODES);
        #pragma unroll
        for (int j = 0; j < 8; j++) conv[j] += v[j];
    }

    if (q != 0) {
        #pragma unroll
        for (int j = 0; j < 8; j++)
            sred[(size_t)(q - 1) * 64 * 9 + ln * 9 + j] = conv[j];
    }
    __syncthreads();
    if (q == 0) {
        #pragma unroll
        for (int j = 0; j < 8; j++) {
            #pragma unroll
            for (int s = 0; s < 3; s++)
                conv[j] += sred[(size_t)s * 64 * 9 + ln * 9 + j];
            conv[j] += __ldg(bc + j);
        }

        float pn = __ldg(b2);
        #pragma unroll 4
        for (int m = 0; m < 32; m++) {
            float h = sb1[m];
            #pragma unroll
            for (int j = 0; j < 8; j++)
                h = fmaf(conv[j], sWeff[j * 32 + m], h);
            h = fmaxf(h, 0.01f * h);    // leaky_relu
            pn = fmaf(h, sW2v[m], pn);
        }
        g_per_node[n] = pn;
    }
}

// ---------------------------------------------------------------------------
// K3: broadcast per_node over 3072 rows. 8 x STG.128 per thread.
// grid = 768 x 256.
// ---------------------------------------------------------------------------
__global__ __launch_bounds__(256) void k_broadcast(float4* __restrict__ out)
{
    const int c  = (blockIdx.x & 1) * 256 + threadIdx.x;
    const int r0 = (blockIdx.x >> 1) * 8;
    const float4 v = __ldg(reinterpret_cast<const float4*>(g_per_node) + c);
    float4* o = out + (size_t)r0 * NF4 + c;
    #pragma unroll
    for (int i = 0; i < 8; i++)
        o[(size_t)i * NF4] = v;
}

// ---------------------------------------------------------------------------
// Inputs: 0:x 1:edge_index(unused) 2:edge_attr(unused) 3:Wc 4:bc 5:W1 6:b1 7:W2 8:b2
// ---------------------------------------------------------------------------
extern "C" void kernel_launch(void* const* d_in, const int* in_sizes, int n_in,
                              void* d_out, int out_size)
{
    const float4* x4 = (const float4*)d_in[0];
    const float*  Wc = (const float*)d_in[3];
    const float*  bc = (const float*)d_in[4];
    const float*  W1 = (const float*)d_in[5];
    const float*  b1 = (const float*)d_in[6];
    const float*  W2 = (const float*)d_in[7];
    const float*  b2 = (const float*)d_in[8];
    float* out = (float*)d_out;

    k_gemm_partial2<<<dim3(NBN, NKC), 256>>>(x4, Wc);
    k_reduce_mlp<<<32, 256>>>(bc, W1, b1, W2, b2);
    k_broadcast<<<768, 256>>>(reinterpret_cast<float4*>(out));
}